// round 9
// baseline (speedup 1.0000x reference)
#include <cuda_runtime.h>
#include <cstdint>

// GeneWiseDecoder: out[b,g] = gelu(gelu(x@W1[g]+b1) @ W2[g] + b2) @ W3[g] + b3
// B=128, LATENT=128, HID=512, GENES=1000, fp32.
// TF32 mma.sync, fp32 accum. 2000 CTAs: gene=bx>>1, 64-row batch half=bx&1.
// 512 threads / 16 warps, warp tile 32x64 (2 m-warps x 8 n-warps), CTA tile 64x512.
// Single 32x512 W buffer in SMEM + register prefetch of the next chunk.

static constexpr int GENES = 1000;
static constexpr int HID   = 512;
static constexpr int LAT   = 128;

static constexpr int PH = 520;   // h1 pitch (520 % 32 == 8 -> conflict-free frags, 16B-aligned rows)
static constexpr int PW = 520;   // W tile pitch

static constexpr int OFF_H  = 0;                      // 64*520   = 33280 floats
static constexpr int OFF_W  = 64 * PH;                // 32*520   = 16640 floats
static constexpr int OFF_B1 = OFF_W + 32 * PW;        // 49920
static constexpr int OFF_B2 = OFF_B1 + 512;           // 50432
static constexpr int OFF_W3 = OFF_B2 + 512;           // 50944
static constexpr int OFF_O  = OFF_W3 + 512;           // 51456
static constexpr int SMEM_FLOATS = OFF_O + 64;        // 51520
static constexpr int SMEM_BYTES  = SMEM_FLOATS * 4;   // 206080 B

__device__ __forceinline__ float to_tf32(float v) {
    uint32_t u;
    asm("cvt.rna.tf32.f32 %0, %1;" : "=r"(u) : "f"(v));
    return __uint_as_float(u);
}

__device__ __forceinline__ uint32_t ld_tf32(const float* __restrict__ p) {
    uint32_t u;
    asm("cvt.rna.tf32.f32 %0, %1;" : "=r"(u) : "f"(*p));
    return u;
}

__device__ __forceinline__ float gelu_exact(float v) {
    return v * normcdff(v);   // jax.nn.gelu(approximate=False)
}

__device__ __forceinline__ void mma_tf32(float d[4], const uint32_t a[4],
                                         uint32_t b0, uint32_t b1) {
    asm volatile(
        "mma.sync.aligned.m16n8k8.row.col.f32.tf32.tf32.f32 "
        "{%0,%1,%2,%3},{%4,%5,%6,%7},{%8,%9},{%0,%1,%2,%3};"
        : "+f"(d[0]), "+f"(d[1]), "+f"(d[2]), "+f"(d[3])
        : "r"(a[0]), "r"(a[1]), "r"(a[2]), "r"(a[3]), "r"(b0), "r"(b1));
}

// Load one 32(K) x 512(N) fp32 tile (ldb = 512) into 8 float4 regs per thread.
__device__ __forceinline__ void load_tile(float4 pre[8], const float* __restrict__ gB,
                                          int k0, int tid) {
#pragma unroll
    for (int i = 0; i < 8; ++i) {
        int idx = tid + i * 512;
        int r = idx >> 7;        // 128 float4 per row
        int c = idx & 127;
        pre[i] = *reinterpret_cast<const float4*>(gB + (size_t)(k0 + r) * 512 + c * 4);
    }
}

// Store register tile to the W SMEM buffer with RNA tf32 rounding (STS.128).
__device__ __forceinline__ void store_tile(float* __restrict__ shW, const float4 pre[8],
                                           int tid) {
#pragma unroll
    for (int i = 0; i < 8; ++i) {
        int idx = tid + i * 512;
        int r = idx >> 7;
        int c = idx & 127;
        float4 t;
        t.x = to_tf32(pre[i].x);
        t.y = to_tf32(pre[i].y);
        t.z = to_tf32(pre[i].z);
        t.w = to_tf32(pre[i].w);
        *reinterpret_cast<float4*>(shW + r * PW + c * 4) = t;
    }
}

// One K=32 chunk of mma, A from SMEM (tf32). Warp tile 32x64 (2 mf x 8 nf).
__device__ __forceinline__ void mma_chunk_sh(float acc[2][8][4],
                                             const float* __restrict__ shA, int kBase,
                                             const float* __restrict__ shW,
                                             int wm, int wn, int grp, int qt) {
    const uint32_t* A = reinterpret_cast<const uint32_t*>(shA);
    const uint32_t* B = reinterpret_cast<const uint32_t*>(shW);
    const int r0 = wm * 32 + grp;
#pragma unroll
    for (int k8 = 0; k8 < 4; ++k8) {
        const int cA = kBase + k8 * 8 + qt;
        uint32_t a[2][4];
#pragma unroll
        for (int mf = 0; mf < 2; ++mf) {
            const int r = r0 + mf * 16;
            a[mf][0] = A[r * PH + cA];
            a[mf][1] = A[(r + 8) * PH + cA];
            a[mf][2] = A[r * PH + cA + 4];
            a[mf][3] = A[(r + 8) * PH + cA + 4];
        }
        const int kl = k8 * 8;
#pragma unroll
        for (int nf = 0; nf < 8; ++nf) {
            const int cb = wn * 64 + nf * 8 + grp;
            uint32_t b0 = B[(kl + qt) * PW + cb];
            uint32_t b1 = B[(kl + 4 + qt) * PW + cb];
            mma_tf32(acc[0][nf], a[0], b0, b1);
            mma_tf32(acc[1][nf], a[1], b0, b1);
        }
    }
}

// One K=32 chunk of mma, A straight from global x (fp32 -> tf32 at load; L1-hot).
__device__ __forceinline__ void mma_chunk_gx(float acc[2][8][4],
                                             const float* __restrict__ xg, int kBase,
                                             const float* __restrict__ shW,
                                             int wm, int wn, int grp, int qt) {
    const uint32_t* B = reinterpret_cast<const uint32_t*>(shW);
    const int r0 = wm * 32 + grp;
#pragma unroll
    for (int k8 = 0; k8 < 4; ++k8) {
        const int cA = kBase + k8 * 8 + qt;
        uint32_t a[2][4];
#pragma unroll
        for (int mf = 0; mf < 2; ++mf) {
            const int r = r0 + mf * 16;
            a[mf][0] = ld_tf32(xg + (size_t)r * LAT + cA);
            a[mf][1] = ld_tf32(xg + (size_t)(r + 8) * LAT + cA);
            a[mf][2] = ld_tf32(xg + (size_t)r * LAT + cA + 4);
            a[mf][3] = ld_tf32(xg + (size_t)(r + 8) * LAT + cA + 4);
        }
        const int kl = k8 * 8;
#pragma unroll
        for (int nf = 0; nf < 8; ++nf) {
            const int cb = wn * 64 + nf * 8 + grp;
            uint32_t b0 = B[(kl + qt) * PW + cb];
            uint32_t b1 = B[(kl + 4 + qt) * PW + cb];
            mma_tf32(acc[0][nf], a[0], b0, b1);
            mma_tf32(acc[1][nf], a[1], b0, b1);
        }
    }
}

__global__ void __launch_bounds__(512, 1)
gene_mlp_kernel(const float* __restrict__ x,
                const float* __restrict__ W1, const float* __restrict__ b1,
                const float* __restrict__ W2, const float* __restrict__ b2,
                const float* __restrict__ W3, const float* __restrict__ b3,
                float* __restrict__ out) {
    extern __shared__ float sm[];
    float* shH  = sm + OFF_H;
    float* shW  = sm + OFF_W;
    float* shB1 = sm + OFF_B1;
    float* shB2 = sm + OFF_B2;
    float* shW3 = sm + OFF_W3;
    float* shO  = sm + OFF_O;

    const int g       = blockIdx.x >> 1;
    const int rowbase = (blockIdx.x & 1) * 64;
    const int tid  = threadIdx.x;
    const int lane = tid & 31;
    const int warp = tid >> 5;       // 0..15
    const int wm = warp >> 3;        // 2 m-warps (32 rows each)
    const int wn = warp & 7;         // 8 n-warps (64 cols each)
    const int grp = lane >> 2;
    const int qt  = lane & 3;

    // ---- stage biases / W3, zero output accumulator ----
    shB1[tid] = b1[(size_t)g * HID + tid];
    shB2[tid] = b2[(size_t)g * HID + tid];
    shW3[tid] = W3[(size_t)g * HID + tid];
    if (tid < 64) shO[tid] = 0.0f;

    const float* xg = x + (size_t)rowbase * LAT;

    // ================= Phase 1: h1 = gelu(x @ W1 + b1) -> shH (tf32) ============
    {
        const float* W1g = W1 + (size_t)g * LAT * HID;
        float acc[2][8][4];
#pragma unroll
        for (int mf = 0; mf < 2; ++mf)
#pragma unroll
            for (int nf = 0; nf < 8; ++nf)
#pragma unroll
                for (int i = 0; i < 4; ++i) acc[mf][nf][i] = 0.0f;

        float4 pre[8];
        load_tile(pre, W1g, 0, tid);
#pragma unroll 1
        for (int kc = 0; kc < 4; ++kc) {
            __syncthreads();                  // prior readers done with shW
            store_tile(shW, pre, tid);
            if (kc + 1 < 4) load_tile(pre, W1g, (kc + 1) * 32, tid);
            __syncthreads();                  // tile visible
            mma_chunk_gx(acc, xg, kc * 32, shW, wm, wn, grp, qt);
        }
        // epilogue: bias + gelu + tf32-store into shH
#pragma unroll
        for (int mf = 0; mf < 2; ++mf)
#pragma unroll
            for (int nf = 0; nf < 8; ++nf)
#pragma unroll
                for (int i = 0; i < 4; ++i) {
                    int row = wm * 32 + mf * 16 + (i >> 1) * 8 + grp;
                    int col = wn * 64 + nf * 8 + 2 * qt + (i & 1);
                    float v = acc[mf][nf][i] + shB1[col];
                    shH[row * PH + col] = to_tf32(gelu_exact(v));
                }
    }

    // ================= Phase 2: h2 = gelu(h1 @ W2 + b2); out += h2 . W3 =========
    {
        const float* W2g = W2 + (size_t)g * HID * HID;
        float acc[2][8][4];
#pragma unroll
        for (int mf = 0; mf < 2; ++mf)
#pragma unroll
            for (int nf = 0; nf < 8; ++nf)
#pragma unroll
                for (int i = 0; i < 4; ++i) acc[mf][nf][i] = 0.0f;

        float4 pre[8];
        load_tile(pre, W2g, 0, tid);
#pragma unroll 1
        for (int kc = 0; kc < 16; ++kc) {
            __syncthreads();                  // readers done with shW; also orders shH writes (kc==0)
            store_tile(shW, pre, tid);
            if (kc + 1 < 16) load_tile(pre, W2g, (kc + 1) * 32, tid);
            __syncthreads();
            mma_chunk_sh(acc, shH, kc * 32, shW, wm, wn, grp, qt);
        }
        // epilogue: bias + gelu + fused dot with W3 (fp32)
        float part[4] = {0.f, 0.f, 0.f, 0.f};
#pragma unroll
        for (int mf = 0; mf < 2; ++mf)
#pragma unroll
            for (int nf = 0; nf < 8; ++nf)
#pragma unroll
                for (int i = 0; i < 4; ++i) {
                    int col = wn * 64 + nf * 8 + 2 * qt + (i & 1);
                    float v = gelu_exact(acc[mf][nf][i] + shB2[col]);
                    part[mf * 2 + (i >> 1)] += v * shW3[col];
                }
#pragma unroll
        for (int r = 0; r < 4; ++r) {
            part[r] += __shfl_xor_sync(0xffffffffu, part[r], 1);
            part[r] += __shfl_xor_sync(0xffffffffu, part[r], 2);
        }
        if (qt == 0) {
#pragma unroll
            for (int r = 0; r < 4; ++r) {
                int row = (r >> 1) * 32 + (r & 1) * 8 + grp;   // wm folded below
                atomicAdd(&shO[wm * 32 + (r & 1) * 8 + (r >> 1) * 16 + grp], part[r]);
                (void)row;
            }
        }
    }

    __syncthreads();
    if (tid < 64) {
        out[(size_t)(rowbase + tid) * GENES + g] = shO[tid] + b3[g];
    }
}

extern "C" void kernel_launch(void* const* d_in, const int* in_sizes, int n_in,
                              void* d_out, int out_size) {
    const float* x  = (const float*)d_in[0];
    const float* W1 = (const float*)d_in[1];
    const float* b1 = (const float*)d_in[2];
    const float* W2 = (const float*)d_in[3];
    const float* b2 = (const float*)d_in[4];
    const float* W3 = (const float*)d_in[5];
    const float* b3 = (const float*)d_in[6];
    float* out = (float*)d_out;

    cudaFuncSetAttribute(gene_mlp_kernel,
                         cudaFuncAttributeMaxDynamicSharedMemorySize, SMEM_BYTES);
    gene_mlp_kernel<<<2 * GENES, 512, SMEM_BYTES>>>(x, W1, b1, W2, b2, W3, b3, out);
}

// round 10
// speedup vs baseline: 1.0382x; 1.0382x over previous
#include <cuda_runtime.h>
#include <cstdint>

// GeneWiseDecoder: out[b,g] = gelu(gelu(x@W1[g]+b1) @ W2[g] + b2) @ W3[g] + b3
// B=128, LATENT=128, HID=512, GENES=1000, fp32.
// TF32 mma.sync, fp32 accum. 2000 CTAs: gene=bx>>1, 64-row batch half=bx&1.
// 512 threads / 16 warps, warp tile 32x64 (2 m-warps x 8 n-warps), CTA tile 64x512.
// W streamed in K=16 chunks, DOUBLE-buffered in SMEM, one __syncthreads per chunk:
//   store(chunk k+1) || prefetch LDG(chunk k+2) || mma(chunk k) -> sync

static constexpr int GENES = 1000;
static constexpr int HID   = 512;
static constexpr int LAT   = 128;

static constexpr int PH = 520;          // pitches: 520 % 32 == 8 -> conflict-free frags
static constexpr int PW = 520;
static constexpr int KCH = 16;          // W chunk K
static constexpr int WCHUNK = KCH * PW; // floats per W buffer (8320)

static constexpr int OFF_H  = 0;                      // 64*520 = 33280 floats
static constexpr int OFF_W  = 64 * PH;                // 2 buffers: 16640 floats
static constexpr int OFF_B1 = OFF_W + 2 * WCHUNK;     // 49920
static constexpr int OFF_B2 = OFF_B1 + 512;           // 50432
static constexpr int OFF_W3 = OFF_B2 + 512;           // 50944
static constexpr int OFF_O  = OFF_W3 + 512;           // 51456
static constexpr int SMEM_FLOATS = OFF_O + 64;        // 51520
static constexpr int SMEM_BYTES  = SMEM_FLOATS * 4;   // 206080 B

__device__ __forceinline__ float to_tf32(float v) {
    uint32_t u;
    asm("cvt.rna.tf32.f32 %0, %1;" : "=r"(u) : "f"(v));
    return __uint_as_float(u);
}

__device__ __forceinline__ uint32_t ld_tf32(const float* __restrict__ p) {
    uint32_t u;
    asm("cvt.rna.tf32.f32 %0, %1;" : "=r"(u) : "f"(*p));
    return u;
}

__device__ __forceinline__ float gelu_exact(float v) {
    return v * normcdff(v);   // jax.nn.gelu(approximate=False)
}

__device__ __forceinline__ void mma_tf32(float d[4], const uint32_t a[4],
                                         uint32_t b0, uint32_t b1) {
    asm volatile(
        "mma.sync.aligned.m16n8k8.row.col.f32.tf32.tf32.f32 "
        "{%0,%1,%2,%3},{%4,%5,%6,%7},{%8,%9},{%0,%1,%2,%3};"
        : "+f"(d[0]), "+f"(d[1]), "+f"(d[2]), "+f"(d[3])
        : "r"(a[0]), "r"(a[1]), "r"(a[2]), "r"(a[3]), "r"(b0), "r"(b1));
}

// Load one 16(K) x 512(N) fp32 tile (ldb = 512) into 4 float4 regs per thread.
__device__ __forceinline__ void load_tile(float4 pre[4], const float* __restrict__ gB,
                                          int k0, int tid) {
#pragma unroll
    for (int i = 0; i < 4; ++i) {
        int idx = tid + i * 512;
        int r = idx >> 7;        // 128 float4 per row
        int c = idx & 127;
        pre[i] = *reinterpret_cast<const float4*>(gB + (size_t)(k0 + r) * 512 + c * 4);
    }
}

// Store register tile to a W SMEM buffer with RNA tf32 rounding (STS.128).
__device__ __forceinline__ void store_tile(float* __restrict__ shW, const float4 pre[4],
                                           int tid) {
#pragma unroll
    for (int i = 0; i < 4; ++i) {
        int idx = tid + i * 512;
        int r = idx >> 7;
        int c = idx & 127;
        float4 t;
        t.x = to_tf32(pre[i].x);
        t.y = to_tf32(pre[i].y);
        t.z = to_tf32(pre[i].z);
        t.w = to_tf32(pre[i].w);
        *reinterpret_cast<float4*>(shW + r * PW + c * 4) = t;
    }
}

// One K=16 chunk of mma, A from SMEM (tf32). Warp tile 32x64 (2 mf x 8 nf).
__device__ __forceinline__ void mma_chunk_sh(float acc[2][8][4],
                                             const float* __restrict__ shA, int kBase,
                                             const float* __restrict__ shW,
                                             int wm, int wn, int grp, int qt) {
    const uint32_t* A = reinterpret_cast<const uint32_t*>(shA);
    const uint32_t* B = reinterpret_cast<const uint32_t*>(shW);
    const int r0 = wm * 32 + grp;
#pragma unroll
    for (int k8 = 0; k8 < 2; ++k8) {
        const int cA = kBase + k8 * 8 + qt;
        uint32_t a[2][4];
#pragma unroll
        for (int mf = 0; mf < 2; ++mf) {
            const int r = r0 + mf * 16;
            a[mf][0] = A[r * PH + cA];
            a[mf][1] = A[(r + 8) * PH + cA];
            a[mf][2] = A[r * PH + cA + 4];
            a[mf][3] = A[(r + 8) * PH + cA + 4];
        }
        const int kl = k8 * 8;
#pragma unroll
        for (int nf = 0; nf < 8; ++nf) {
            const int cb = wn * 64 + nf * 8 + grp;
            uint32_t b0 = B[(kl + qt) * PW + cb];
            uint32_t b1 = B[(kl + 4 + qt) * PW + cb];
            mma_tf32(acc[0][nf], a[0], b0, b1);
            mma_tf32(acc[1][nf], a[1], b0, b1);
        }
    }
}

// One K=16 chunk of mma, A straight from global x (fp32 -> tf32 at load; L1/L2-hot).
__device__ __forceinline__ void mma_chunk_gx(float acc[2][8][4],
                                             const float* __restrict__ xg, int kBase,
                                             const float* __restrict__ shW,
                                             int wm, int wn, int grp, int qt) {
    const uint32_t* B = reinterpret_cast<const uint32_t*>(shW);
    const int r0 = wm * 32 + grp;
#pragma unroll
    for (int k8 = 0; k8 < 2; ++k8) {
        const int cA = kBase + k8 * 8 + qt;
        uint32_t a[2][4];
#pragma unroll
        for (int mf = 0; mf < 2; ++mf) {
            const int r = r0 + mf * 16;
            a[mf][0] = ld_tf32(xg + (size_t)r * LAT + cA);
            a[mf][1] = ld_tf32(xg + (size_t)(r + 8) * LAT + cA);
            a[mf][2] = ld_tf32(xg + (size_t)r * LAT + cA + 4);
            a[mf][3] = ld_tf32(xg + (size_t)(r + 8) * LAT + cA + 4);
        }
        const int kl = k8 * 8;
#pragma unroll
        for (int nf = 0; nf < 8; ++nf) {
            const int cb = wn * 64 + nf * 8 + grp;
            uint32_t b0 = B[(kl + qt) * PW + cb];
            uint32_t b1 = B[(kl + 4 + qt) * PW + cb];
            mma_tf32(acc[0][nf], a[0], b0, b1);
            mma_tf32(acc[1][nf], a[1], b0, b1);
        }
    }
}

__global__ void __launch_bounds__(512, 1)
gene_mlp_kernel(const float* __restrict__ x,
                const float* __restrict__ W1, const float* __restrict__ b1,
                const float* __restrict__ W2, const float* __restrict__ b2,
                const float* __restrict__ W3, const float* __restrict__ b3,
                float* __restrict__ out) {
    extern __shared__ float sm[];
    float* shH  = sm + OFF_H;
    float* shW  = sm + OFF_W;
    float* shB1 = sm + OFF_B1;
    float* shB2 = sm + OFF_B2;
    float* shW3 = sm + OFF_W3;
    float* shO  = sm + OFF_O;

    const int g       = blockIdx.x >> 1;
    const int rowbase = (blockIdx.x & 1) * 64;
    const int tid  = threadIdx.x;
    const int lane = tid & 31;
    const int warp = tid >> 5;       // 0..15
    const int wm = warp >> 3;        // 2 m-warps (32 rows each)
    const int wn = warp & 7;         // 8 n-warps (64 cols each)
    const int grp = lane >> 2;
    const int qt  = lane & 3;

    // ---- stage biases / W3, zero output accumulator ----
    shB1[tid] = b1[(size_t)g * HID + tid];
    shB2[tid] = b2[(size_t)g * HID + tid];
    shW3[tid] = W3[(size_t)g * HID + tid];
    if (tid < 64) shO[tid] = 0.0f;

    const float* xg = x + (size_t)rowbase * LAT;

    // ================= Phase 1: h1 = gelu(x @ W1 + b1) -> shH (tf32) ============
    {
        const float* W1g = W1 + (size_t)g * LAT * HID;
        constexpr int NC = LAT / KCH;   // 8 chunks
        float acc[2][8][4];
#pragma unroll
        for (int mf = 0; mf < 2; ++mf)
#pragma unroll
            for (int nf = 0; nf < 8; ++nf)
#pragma unroll
                for (int i = 0; i < 4; ++i) acc[mf][nf][i] = 0.0f;

        float4 pre[4];
        load_tile(pre, W1g, 0, tid);
        store_tile(shW, pre, tid);                 // chunk 0 -> buf 0
        load_tile(pre, W1g, KCH, tid);             // chunk 1 -> regs
        __syncthreads();
#pragma unroll 1
        for (int kc = 0; kc < NC; ++kc) {
            if (kc + 1 < NC) store_tile(shW + ((kc + 1) & 1) * WCHUNK, pre, tid);
            if (kc + 2 < NC) load_tile(pre, W1g, (kc + 2) * KCH, tid);
            mma_chunk_gx(acc, xg, kc * KCH, shW + (kc & 1) * WCHUNK, wm, wn, grp, qt);
            __syncthreads();
        }
        // epilogue: bias + gelu + tf32-store into shH
#pragma unroll
        for (int mf = 0; mf < 2; ++mf)
#pragma unroll
            for (int nf = 0; nf < 8; ++nf)
#pragma unroll
                for (int i = 0; i < 4; ++i) {
                    int row = wm * 32 + mf * 16 + (i >> 1) * 8 + grp;
                    int col = wn * 64 + nf * 8 + 2 * qt + (i & 1);
                    float v = acc[mf][nf][i] + shB1[col];
                    shH[row * PH + col] = to_tf32(gelu_exact(v));
                }
    }

    // ================= Phase 2: h2 = gelu(h1 @ W2 + b2); out += h2 . W3 =========
    {
        const float* W2g = W2 + (size_t)g * HID * HID;
        constexpr int NC = HID / KCH;   // 32 chunks
        float acc[2][8][4];
#pragma unroll
        for (int mf = 0; mf < 2; ++mf)
#pragma unroll
            for (int nf = 0; nf < 8; ++nf)
#pragma unroll
                for (int i = 0; i < 4; ++i) acc[mf][nf][i] = 0.0f;

        float4 pre[4];
        load_tile(pre, W2g, 0, tid);
        store_tile(shW, pre, tid);
        load_tile(pre, W2g, KCH, tid);
        __syncthreads();                            // also orders phase-1 shH writes
#pragma unroll 1
        for (int kc = 0; kc < NC; ++kc) {
            if (kc + 1 < NC) store_tile(shW + ((kc + 1) & 1) * WCHUNK, pre, tid);
            if (kc + 2 < NC) load_tile(pre, W2g, (kc + 2) * KCH, tid);
            mma_chunk_sh(acc, shH, kc * KCH, shW + (kc & 1) * WCHUNK, wm, wn, grp, qt);
            __syncthreads();
        }
        // epilogue: bias + gelu + fused dot with W3 (fp32)
        float part[4] = {0.f, 0.f, 0.f, 0.f};
#pragma unroll
        for (int mf = 0; mf < 2; ++mf)
#pragma unroll
            for (int nf = 0; nf < 8; ++nf)
#pragma unroll
                for (int i = 0; i < 4; ++i) {
                    int col = wn * 64 + nf * 8 + 2 * qt + (i & 1);
                    float v = gelu_exact(acc[mf][nf][i] + shB2[col]);
                    part[mf * 2 + (i >> 1)] += v * shW3[col];
                }
#pragma unroll
        for (int r = 0; r < 4; ++r) {
            part[r] += __shfl_xor_sync(0xffffffffu, part[r], 1);
            part[r] += __shfl_xor_sync(0xffffffffu, part[r], 2);
        }
        if (qt == 0) {
#pragma unroll
            for (int r = 0; r < 4; ++r) {
                // part[r] belongs to row wm*32 + (r>>1)*16 + (r&1)*8 + grp
                atomicAdd(&shO[wm * 32 + (r >> 1) * 16 + (r & 1) * 8 + grp], part[r]);
            }
        }
    }

    __syncthreads();
    if (tid < 64) {
        out[(size_t)(rowbase + tid) * GENES + g] = shO[tid] + b3[g];
    }
}

extern "C" void kernel_launch(void* const* d_in, const int* in_sizes, int n_in,
                              void* d_out, int out_size) {
    const float* x  = (const float*)d_in[0];
    const float* W1 = (const float*)d_in[1];
    const float* b1 = (const float*)d_in[2];
    const float* W2 = (const float*)d_in[3];
    const float* b2 = (const float*)d_in[4];
    const float* W3 = (const float*)d_in[5];
    const float* b3 = (const float*)d_in[6];
    float* out = (float*)d_out;

    cudaFuncSetAttribute(gene_mlp_kernel,
                         cudaFuncAttributeMaxDynamicSharedMemorySize, SMEM_BYTES);
    gene_mlp_kernel<<<2 * GENES, 512, SMEM_BYTES>>>(x, W1, b1, W2, b2, W3, b3, out);
}